// round 10
// baseline (speedup 1.0000x reference)
#include <cuda_runtime.h>
#include <cuda_bf16.h>
#include <cstdint>

// S4D via mma.sync bf16 (3x split), R10:
//  - ldmatrix.x4 fragment loads (24 LDSM/warp vs 96 LDS + addr ALU)
//  - compile-time-folded swizzle offsets in phase-1 stores
//  - grid H/2, 2 h per block -> single full wave (no 38%-full tail)
//
// Per h:  K[m + 128c] = sum_k QT[c,k] * PT[m,k]
//   PT[m,2n] = Re(2*Ck_n*w_n^m),  PT[m,2n+1] = Im(...)
//   QT[c,2n] = Re((w_n^128)^c),   QT[c,2n+1] = -Im(...)
// GEMM M=32(c) x N=128(m) x K=64, mma.m16n8k16.row.col, fp32 acc.
// Tiles k-major, 128B rows, 16B-chunk swizzle: chunk ^= (row & 7).

typedef uint32_t u32;

#define PPLANE 16384   // bytes per P plane (128 x 64 bf16)
#define QPLANE  4096   // bytes per Q plane ( 32 x 64 bf16)

__device__ __forceinline__ u32 smem_u32(const void* p) {
    u32 a;
    asm("{ .reg .u64 t; cvta.to.shared.u64 t, %1; cvt.u32.u64 %0, t; }"
        : "=r"(a) : "l"(p));
    return a;
}

__device__ __forceinline__ void ldsm4(u32 addr, u32* r) {
    asm volatile("ldmatrix.sync.aligned.m8n8.x4.shared.b16 {%0,%1,%2,%3}, [%4];"
                 : "=r"(r[0]), "=r"(r[1]), "=r"(r[2]), "=r"(r[3]) : "r"(addr));
}

__device__ __forceinline__ void mma_bf16(float* d, const u32* a, u32 b0, u32 b1) {
    asm volatile(
        "mma.sync.aligned.m16n8k16.row.col.f32.bf16.bf16.f32 "
        "{%0,%1,%2,%3}, {%4,%5,%6,%7}, {%8,%9}, {%0,%1,%2,%3};"
        : "+f"(d[0]), "+f"(d[1]), "+f"(d[2]), "+f"(d[3])
        : "r"(a[0]), "r"(a[1]), "r"(a[2]), "r"(a[3]), "r"(b0), "r"(b1));
}

// hi/lo bf16 split store: hi at base+off, lo at base+off+plane
__device__ __forceinline__ void split_store(char* base, u32 off, int plane,
                                            float x, float y) {
    __nv_bfloat162 h = __float22bfloat162_rn(make_float2(x, y));
    float xl = x - __bfloat162float(h.x);
    float yl = y - __bfloat162float(h.y);
    __nv_bfloat162 l = __float22bfloat162_rn(make_float2(xl, yl));
    *reinterpret_cast<__nv_bfloat162*>(base + off)         = h;
    *reinterpret_cast<__nv_bfloat162*>(base + off + plane) = l;
}

__global__ __launch_bounds__(256)
void s4d_kernel(const float* __restrict__ log_dt,
                const float* __restrict__ C,
                const float* __restrict__ log_A_real,
                const float* __restrict__ A_imag,
                float* __restrict__ out,
                int HB)   // blocks = H/2
{
    __shared__ __align__(128) __nv_bfloat16 sP[2][128 * 64];  // hi, lo  32 KB
    __shared__ __align__(128) __nv_bfloat16 sQ[2][ 32 * 64];  // hi, lo   8 KB

    const int tid  = threadIdx.x;
    const int lane = tid & 31;
    const int wrp  = tid >> 5;

    // ---- phase-2 lane constants (h-invariant): fragment base addresses ----
    const int gid = lane >> 2;
    const int tig = lane & 3;
    const int r0  = 16 * (wrp & 1);        // A (c-dim) tile base
    const int jb  = 4 * (wrp >> 1);        // B (m-dim) tile group base

    u32 aaddr[4], baddr[2][4];
    {
        const u32 Qb = smem_u32(sQ);
        const u32 Pb = smem_u32(sP);
        // A: row = r0 + (lane&15), k-half = lane>>4
        {
            const u32 row = (u32)(r0 + (lane & 15));
            const u32 hh  = (u32)(lane >> 4);
            const u32 rt  = Qb + row * 128u;
            const u32 x   = row & 7u;
            #pragma unroll
            for (int kc = 0; kc < 4; kc++)
                aaddr[kc] = rt + ((((2u * kc + hh) ^ x)) << 4);
        }
        // B group g covers j = jb+2g + (lane>>4); k-half = (lane>>3)&1
        #pragma unroll
        for (int g = 0; g < 2; g++) {
            const u32 row = 8u * (u32)(jb + 2 * g + (lane >> 4)) + (lane & 7u);
            const u32 hb  = (u32)((lane >> 3) & 1);
            const u32 rt  = Pb + row * 128u;
            const u32 x   = row & 7u;
            #pragma unroll
            for (int kc = 0; kc < 4; kc++)
                baddr[g][kc] = rt + ((((2u * kc + hb) ^ x)) << 4);
        }
    }

    for (int it = 0; it < 2; it++) {
        const int h = blockIdx.x + it * HB;
        if (it) __syncthreads();   // previous phase-2 reads done before overwrite

        // ================= Phase 1: build swizzled bf16 hi/lo tiles ========
        {
            const int n = tid & 31;          // mode
            const int s = tid >> 5;          // slice 0..7
            const float dt = expf(log_dt[h]);

            const float Ar = -expf(log_A_real[h * 32 + n]);
            const float Ai = A_imag[h * 32 + n];
            const float dr = dt * Ar, di = dt * Ai;

            float er, sn, cs;

            er = expf(dr); sincosf(di, &sn, &cs);
            const float wr = er * cs, wi = er * sn;

            const float inv = 1.0f / (Ar * Ar + Ai * Ai);
            const float nr = wr - 1.0f, ni = wi;
            const float gr = (nr * Ar + ni * Ai) * inv;
            const float gi = (ni * Ar - nr * Ai) * inv;
            const float Cr = C[(h * 32 + n) * 2 + 0];
            const float Ci = C[(h * 32 + n) * 2 + 1];
            const float p0r = 2.0f * (Cr * gr - Ci * gi);
            const float p0i = 2.0f * (Cr * gi + Ci * gr);

            const u32 kb   = 4u * (u32)n;             // k-byte of this mode
            const u32 colb = ((u32)(n >> 2) << 4) | (kb & 15u);

            // ---- PT rows m in [16s,16s+16): row&7 = k&7 (16s = 0 mod 8) ----
            {
                const float m0 = (float)(16 * s);
                er = expf(dr * m0); sincosf(di * m0, &sn, &cs);
                float pr = p0r * (er * cs) - p0i * (er * sn);
                float pi = p0r * (er * sn) + p0i * (er * cs);

                char* Pc = (char*)sP;
                const u32 pbase = (u32)(16 * s) * 128u + colb;
                #pragma unroll
                for (int k = 0; k < 16; k++) {
                    const u32 off = (pbase ^ (((u32)(k & 7)) << 4)) + (u32)k * 128u;
                    split_store(Pc, off, PPLANE, pr, pi);
                    const float t = pr * wr - pi * wi;
                    pi = pr * wi + pi * wr;
                    pr = t;
                }
            }

            // ---- QT rows c in [4s,4s+4): row&7 = 4(s&1)+k ----
            {
                er = expf(128.0f * dr); sincosf(128.0f * di, &sn, &cs);
                const float wCr = er * cs, wCi = er * sn;

                const float c0 = 512.0f * (float)s;
                er = expf(dr * c0); sincosf(di * c0, &sn, &cs);
                float qr = er * cs, qi = er * sn;

                char* Qc = (char*)sQ;
                const u32 qbase = (u32)(4 * s) * 128u + colb;
                const u32 xq    = 4u * (u32)(s & 1);
                #pragma unroll
                for (int k = 0; k < 4; k++) {
                    const u32 off = (qbase ^ ((xq + (u32)k) << 4)) + (u32)k * 128u;
                    split_store(Qc, off, QPLANE, qr, -qi);
                    const float t = qr * wCr - qi * wCi;
                    qi = qr * wCi + qi * wCr;
                    qr = t;
                }
            }
        }
        __syncthreads();

        // ================= Phase 2: ldmatrix + mma.sync ====================
        float acc[4][4];
        #pragma unroll
        for (int j = 0; j < 4; j++)
            #pragma unroll
            for (int r = 0; r < 4; r++) acc[j][r] = 0.0f;

        #pragma unroll
        for (int kc = 0; kc < 4; kc++) {
            u32 ahi[4], alo[4], bh[2][4], bl[2][4];
            ldsm4(aaddr[kc],          ahi);
            ldsm4(aaddr[kc] + QPLANE, alo);
            ldsm4(baddr[0][kc],           bh[0]);
            ldsm4(baddr[0][kc] + PPLANE,  bl[0]);
            ldsm4(baddr[1][kc],           bh[1]);
            ldsm4(baddr[1][kc] + PPLANE,  bl[1]);

            #pragma unroll
            for (int jj = 0; jj < 4; jj++) {
                const int g = jj >> 1, o = (jj & 1) * 2;
                mma_bf16(acc[jj], ahi, bh[g][o], bh[g][o + 1]);   // hi*hi
                mma_bf16(acc[jj], ahi, bl[g][o], bl[g][o + 1]);   // hi*lo
                mma_bf16(acc[jj], alo, bh[g][o], bh[g][o + 1]);   // lo*hi
            }
        }

        // ---- store D fragments: c = r0+gid (+8), m = 8*(jb+jj) + 2*tig ----
        float* o = out + (size_t)h * 4096;
        #pragma unroll
        for (int jj = 0; jj < 4; jj++) {
            const int m = 8 * (jb + jj) + 2 * tig;
            const int c = r0 + gid;
            *reinterpret_cast<float2*>(o + c * 128 + m) =
                make_float2(acc[jj][0], acc[jj][1]);
            *reinterpret_cast<float2*>(o + (c + 8) * 128 + m) =
                make_float2(acc[jj][2], acc[jj][3]);
        }
    }
}

extern "C" void kernel_launch(void* const* d_in, const int* in_sizes, int n_in,
                              void* d_out, int out_size)
{
    const float* log_dt     = (const float*)d_in[0];
    const float* C          = (const float*)d_in[1];
    const float* log_A_real = (const float*)d_in[2];
    const float* A_imag     = (const float*)d_in[3];
    float*       out        = (float*)d_out;

    const int H  = in_sizes[0];   // 1024
    const int HB = H / 2;         // 512 blocks, 2 h each -> single wave
    s4d_kernel<<<HB, 256>>>(log_dt, C, log_A_real, A_imag, out, HB);
}

// round 11
// speedup vs baseline: 1.5265x; 1.5265x over previous
#include <cuda_runtime.h>
#include <cuda_bf16.h>
#include <cstdint>

// S4D via mma.sync bf16 (3x split), R11:
//  R10's ldmatrix.x4 fragment loads + folded-swizzle phase-1 stores,
//  with the grid reverted to one h per block (H blocks) — the R10 2-h
//  serialization starved resident parallelism and regressed.
//
// Per h:  K[m + 128c] = sum_k QT[c,k] * PT[m,k]
//   PT[m,2n] = Re(2*Ck_n*w_n^m),  PT[m,2n+1] = Im(...)
//   QT[c,2n] = Re((w_n^128)^c),   QT[c,2n+1] = -Im(...)
// GEMM M=32(c) x N=128(m) x K=64, mma.m16n8k16.row.col, fp32 acc.
// Tiles k-major, 128B rows, 16B-chunk swizzle: chunk ^= (row & 7).

typedef uint32_t u32;

#define PPLANE 16384   // bytes per P plane (128 x 64 bf16)
#define QPLANE  4096   // bytes per Q plane ( 32 x 64 bf16)

__device__ __forceinline__ u32 smem_u32(const void* p) {
    u32 a;
    asm("{ .reg .u64 t; cvta.to.shared.u64 t, %1; cvt.u32.u64 %0, t; }"
        : "=r"(a) : "l"(p));
    return a;
}

__device__ __forceinline__ void ldsm4(u32 addr, u32* r) {
    asm volatile("ldmatrix.sync.aligned.m8n8.x4.shared.b16 {%0,%1,%2,%3}, [%4];"
                 : "=r"(r[0]), "=r"(r[1]), "=r"(r[2]), "=r"(r[3]) : "r"(addr));
}

__device__ __forceinline__ void mma_bf16(float* d, const u32* a, u32 b0, u32 b1) {
    asm volatile(
        "mma.sync.aligned.m16n8k16.row.col.f32.bf16.bf16.f32 "
        "{%0,%1,%2,%3}, {%4,%5,%6,%7}, {%8,%9}, {%0,%1,%2,%3};"
        : "+f"(d[0]), "+f"(d[1]), "+f"(d[2]), "+f"(d[3])
        : "r"(a[0]), "r"(a[1]), "r"(a[2]), "r"(a[3]), "r"(b0), "r"(b1));
}

// hi/lo bf16 split store: hi at base+off, lo at base+off+plane
__device__ __forceinline__ void split_store(char* base, u32 off, int plane,
                                            float x, float y) {
    __nv_bfloat162 h = __float22bfloat162_rn(make_float2(x, y));
    float xl = x - __bfloat162float(h.x);
    float yl = y - __bfloat162float(h.y);
    __nv_bfloat162 l = __float22bfloat162_rn(make_float2(xl, yl));
    *reinterpret_cast<__nv_bfloat162*>(base + off)         = h;
    *reinterpret_cast<__nv_bfloat162*>(base + off + plane) = l;
}

__global__ __launch_bounds__(256)
void s4d_kernel(const float* __restrict__ log_dt,
                const float* __restrict__ C,
                const float* __restrict__ log_A_real,
                const float* __restrict__ A_imag,
                float* __restrict__ out)
{
    __shared__ __align__(128) __nv_bfloat16 sP[2][128 * 64];  // hi, lo  32 KB
    __shared__ __align__(128) __nv_bfloat16 sQ[2][ 32 * 64];  // hi, lo   8 KB

    const int h    = blockIdx.x;
    const int tid  = threadIdx.x;
    const int lane = tid & 31;
    const int wrp  = tid >> 5;

    // ================= Phase 1: build swizzled bf16 hi/lo tiles ============
    {
        const int n = tid & 31;          // mode
        const int s = tid >> 5;          // slice 0..7
        const float dt = expf(log_dt[h]);

        const float Ar = -expf(log_A_real[h * 32 + n]);
        const float Ai = A_imag[h * 32 + n];
        const float dr = dt * Ar, di = dt * Ai;

        float er, sn, cs;

        er = expf(dr); sincosf(di, &sn, &cs);
        const float wr = er * cs, wi = er * sn;

        const float inv = 1.0f / (Ar * Ar + Ai * Ai);
        const float nr = wr - 1.0f, ni = wi;
        const float gr = (nr * Ar + ni * Ai) * inv;
        const float gi = (ni * Ar - nr * Ai) * inv;
        const float Cr = C[(h * 32 + n) * 2 + 0];
        const float Ci = C[(h * 32 + n) * 2 + 1];
        const float p0r = 2.0f * (Cr * gr - Ci * gi);
        const float p0i = 2.0f * (Cr * gi + Ci * gr);

        const u32 kb   = 4u * (u32)n;             // k-byte of this mode
        const u32 colb = ((u32)(n >> 2) << 4) | (kb & 15u);

        // ---- PT rows m in [16s,16s+16): row&7 = k&7 (16s = 0 mod 8) ----
        {
            const float m0 = (float)(16 * s);
            er = expf(dr * m0); sincosf(di * m0, &sn, &cs);
            float pr = p0r * (er * cs) - p0i * (er * sn);
            float pi = p0r * (er * sn) + p0i * (er * cs);

            char* Pc = (char*)sP;
            const u32 pbase = (u32)(16 * s) * 128u + colb;
            #pragma unroll
            for (int k = 0; k < 16; k++) {
                const u32 off = (pbase ^ (((u32)(k & 7)) << 4)) + (u32)k * 128u;
                split_store(Pc, off, PPLANE, pr, pi);
                const float t = pr * wr - pi * wi;
                pi = pr * wi + pi * wr;
                pr = t;
            }
        }

        // ---- QT rows c in [4s,4s+4): row&7 = 4(s&1)+k ----
        {
            er = expf(128.0f * dr); sincosf(128.0f * di, &sn, &cs);
            const float wCr = er * cs, wCi = er * sn;

            const float c0 = 512.0f * (float)s;
            er = expf(dr * c0); sincosf(di * c0, &sn, &cs);
            float qr = er * cs, qi = er * sn;

            char* Qc = (char*)sQ;
            const u32 qbase = (u32)(4 * s) * 128u + colb;
            const u32 xq    = 4u * (u32)(s & 1);
            #pragma unroll
            for (int k = 0; k < 4; k++) {
                const u32 off = (qbase ^ ((xq + (u32)k) << 4)) + (u32)k * 128u;
                split_store(Qc, off, QPLANE, qr, -qi);
                const float t = qr * wCr - qi * wCi;
                qi = qr * wCi + qi * wCr;
                qr = t;
            }
        }
    }
    __syncthreads();

    // ================= Phase 2: ldmatrix + mma.sync ========================
    const int gid = lane >> 2;
    const int tig = lane & 3;
    const int r0  = 16 * (wrp & 1);        // A (c-dim) tile base
    const int jb  = 4 * (wrp >> 1);        // B (m-dim) tile group base

    u32 aaddr[4], baddr[2][4];
    {
        const u32 Qb = smem_u32(sQ);
        const u32 Pb = smem_u32(sP);
        // A: row = r0 + (lane&15), k-half = lane>>4
        {
            const u32 row = (u32)(r0 + (lane & 15));
            const u32 hh  = (u32)(lane >> 4);
            const u32 rt  = Qb + row * 128u;
            const u32 x   = row & 7u;
            #pragma unroll
            for (int kc = 0; kc < 4; kc++)
                aaddr[kc] = rt + ((((2u * kc + hh) ^ x)) << 4);
        }
        // B group g covers j = jb+2g + (lane>>4); k-half = (lane>>3)&1
        #pragma unroll
        for (int g = 0; g < 2; g++) {
            const u32 row = 8u * (u32)(jb + 2 * g + (lane >> 4)) + (lane & 7u);
            const u32 hb  = (u32)((lane >> 3) & 1);
            const u32 rt  = Pb + row * 128u;
            const u32 x   = row & 7u;
            #pragma unroll
            for (int kc = 0; kc < 4; kc++)
                baddr[g][kc] = rt + ((((2u * kc + hb) ^ x)) << 4);
        }
    }

    float acc[4][4];
    #pragma unroll
    for (int j = 0; j < 4; j++)
        #pragma unroll
        for (int r = 0; r < 4; r++) acc[j][r] = 0.0f;

    #pragma unroll
    for (int kc = 0; kc < 4; kc++) {
        u32 ahi[4], alo[4], bh[2][4], bl[2][4];
        ldsm4(aaddr[kc],          ahi);
        ldsm4(aaddr[kc] + QPLANE, alo);
        ldsm4(baddr[0][kc],           bh[0]);
        ldsm4(baddr[0][kc] + PPLANE,  bl[0]);
        ldsm4(baddr[1][kc],           bh[1]);
        ldsm4(baddr[1][kc] + PPLANE,  bl[1]);

        #pragma unroll
        for (int jj = 0; jj < 4; jj++) {
            const int g = jj >> 1, o = (jj & 1) * 2;
            mma_bf16(acc[jj], ahi, bh[g][o], bh[g][o + 1]);   // hi*hi
            mma_bf16(acc[jj], ahi, bl[g][o], bl[g][o + 1]);   // hi*lo
            mma_bf16(acc[jj], alo, bh[g][o], bh[g][o + 1]);   // lo*hi
        }
    }

    // ---- store D fragments: c = r0+gid (+8), m = 8*(jb+jj) + 2*tig ----
    float* o = out + (size_t)h * 4096;
    #pragma unroll
    for (int jj = 0; jj < 4; jj++) {
        const int m = 8 * (jb + jj) + 2 * tig;
        const int c = r0 + gid;
        *reinterpret_cast<float2*>(o + c * 128 + m) =
            make_float2(acc[jj][0], acc[jj][1]);
        *reinterpret_cast<float2*>(o + (c + 8) * 128 + m) =
            make_float2(acc[jj][2], acc[jj][3]);
    }
}

extern "C" void kernel_launch(void* const* d_in, const int* in_sizes, int n_in,
                              void* d_out, int out_size)
{
    const float* log_dt     = (const float*)d_in[0];
    const float* C          = (const float*)d_in[1];
    const float* log_A_real = (const float*)d_in[2];
    const float* A_imag     = (const float*)d_in[3];
    float*       out        = (float*)d_out;

    const int H = in_sizes[0];   // 1024
    s4d_kernel<<<H, 256>>>(log_dt, C, log_A_real, A_imag, out);
}

// round 12
// speedup vs baseline: 1.5529x; 1.0173x over previous
#include <cuda_runtime.h>
#include <cuda_bf16.h>
#include <cstdint>

// S4D via mma.sync bf16 (3x split), R12:
//  512-thread blocks (one h per block): phase-1 serial chains halved
//  (8-row P slices), phase-2 split across 16 warps (24 MMA each),
//  __launch_bounds__(512,3) -> 48 warps/SM target.
//
// Per h:  K[m + 128c] = sum_k QT[c,k] * PT[m,k]
//   PT[m,2n] = Re(2*Ck_n*w_n^m),  PT[m,2n+1] = Im(...)
//   QT[c,2n] = Re((w_n^128)^c),   QT[c,2n+1] = -Im(...)
// GEMM M=32(c) x N=128(m) x K=64, mma.m16n8k16.row.col, fp32 acc.
// Tiles k-major, 128B rows, 16B-chunk swizzle: chunk ^= (row & 7).

typedef uint32_t u32;

#define PPLANE 16384   // bytes per P plane (128 x 64 bf16)
#define QPLANE  4096   // bytes per Q plane ( 32 x 64 bf16)

__device__ __forceinline__ u32 smem_u32(const void* p) {
    u32 a;
    asm("{ .reg .u64 t; cvta.to.shared.u64 t, %1; cvt.u32.u64 %0, t; }"
        : "=r"(a) : "l"(p));
    return a;
}

__device__ __forceinline__ void ldsm4(u32 addr, u32* r) {
    asm volatile("ldmatrix.sync.aligned.m8n8.x4.shared.b16 {%0,%1,%2,%3}, [%4];"
                 : "=r"(r[0]), "=r"(r[1]), "=r"(r[2]), "=r"(r[3]) : "r"(addr));
}

__device__ __forceinline__ void mma_bf16(float* d, const u32* a, u32 b0, u32 b1) {
    asm volatile(
        "mma.sync.aligned.m16n8k16.row.col.f32.bf16.bf16.f32 "
        "{%0,%1,%2,%3}, {%4,%5,%6,%7}, {%8,%9}, {%0,%1,%2,%3};"
        : "+f"(d[0]), "+f"(d[1]), "+f"(d[2]), "+f"(d[3])
        : "r"(a[0]), "r"(a[1]), "r"(a[2]), "r"(a[3]), "r"(b0), "r"(b1));
}

// hi/lo bf16 split store: hi at base+off, lo at base+off+plane
__device__ __forceinline__ void split_store(char* base, u32 off, int plane,
                                            float x, float y) {
    __nv_bfloat162 h = __float22bfloat162_rn(make_float2(x, y));
    float xl = x - __bfloat162float(h.x);
    float yl = y - __bfloat162float(h.y);
    __nv_bfloat162 l = __float22bfloat162_rn(make_float2(xl, yl));
    *reinterpret_cast<__nv_bfloat162*>(base + off)         = h;
    *reinterpret_cast<__nv_bfloat162*>(base + off + plane) = l;
}

__global__ __launch_bounds__(512, 3)
void s4d_kernel(const float* __restrict__ log_dt,
                const float* __restrict__ C,
                const float* __restrict__ log_A_real,
                const float* __restrict__ A_imag,
                float* __restrict__ out)
{
    __shared__ __align__(128) __nv_bfloat16 sP[2][128 * 64];  // hi, lo  32 KB
    __shared__ __align__(128) __nv_bfloat16 sQ[2][ 32 * 64];  // hi, lo   8 KB

    const int h    = blockIdx.x;
    const int tid  = threadIdx.x;
    const int lane = tid & 31;
    const int wrp  = tid >> 5;   // 0..15

    // ================= Phase 1: build swizzled bf16 hi/lo tiles ============
    {
        const int n = tid & 31;          // mode
        const int s = tid >> 5;          // slice 0..15
        const float dt = expf(log_dt[h]);

        const float Ar = -expf(log_A_real[h * 32 + n]);
        const float Ai = A_imag[h * 32 + n];
        const float dr = dt * Ar, di = dt * Ai;

        float er, sn, cs;

        er = expf(dr); sincosf(di, &sn, &cs);
        const float wr = er * cs, wi = er * sn;

        const float inv = 1.0f / (Ar * Ar + Ai * Ai);
        const float nr = wr - 1.0f, ni = wi;
        const float gr = (nr * Ar + ni * Ai) * inv;
        const float gi = (ni * Ar - nr * Ai) * inv;
        const float Cr = C[(h * 32 + n) * 2 + 0];
        const float Ci = C[(h * 32 + n) * 2 + 1];
        const float p0r = 2.0f * (Cr * gr - Ci * gi);
        const float p0i = 2.0f * (Cr * gi + Ci * gr);

        const u32 kb   = 4u * (u32)n;             // k-byte of this mode
        const u32 colb = ((u32)(n >> 2) << 4) | (kb & 15u);

        // ---- PT rows m in [8s, 8s+8): row&7 = k (8s = 0 mod 8) ----
        {
            const float m0 = (float)(8 * s);
            er = expf(dr * m0); sincosf(di * m0, &sn, &cs);
            float pr = p0r * (er * cs) - p0i * (er * sn);
            float pi = p0r * (er * sn) + p0i * (er * cs);

            char* Pc = (char*)sP;
            const u32 pbase = (u32)(8 * s) * 128u + colb;
            #pragma unroll
            for (int k = 0; k < 8; k++) {
                const u32 off = (pbase ^ (((u32)k) << 4)) + (u32)k * 128u;
                split_store(Pc, off, PPLANE, pr, pi);
                const float t = pr * wr - pi * wi;
                pi = pr * wi + pi * wr;
                pr = t;
            }
        }

        // ---- QT rows c in [2s, 2s+2): row&7 = 2(s&3)+k ----
        {
            er = expf(128.0f * dr); sincosf(128.0f * di, &sn, &cs);
            const float wCr = er * cs, wCi = er * sn;

            const float c0 = 256.0f * (float)s;   // exp(128*dtA * 2s)
            er = expf(dr * c0); sincosf(di * c0, &sn, &cs);
            float qr = er * cs, qi = er * sn;

            char* Qc = (char*)sQ;
            const u32 qbase = (u32)(2 * s) * 128u + colb;
            const u32 xq    = 2u * (u32)(s & 3);
            #pragma unroll
            for (int k = 0; k < 2; k++) {
                const u32 off = (qbase ^ ((xq + (u32)k) << 4)) + (u32)k * 128u;
                split_store(Qc, off, QPLANE, qr, -qi);
                const float t = qr * wCr - qi * wCi;
                qi = qr * wCi + qi * wCr;
                qr = t;
            }
        }
    }
    __syncthreads();

    // ================= Phase 2: ldmatrix + mma.sync ========================
    // 16 warps: c-half r0 = 16*(wrp&1), m j-pair jp = wrp>>1 (j = 2jp, 2jp+1)
    const int gid = lane >> 2;
    const int tig = lane & 3;
    const int r0  = 16 * (wrp & 1);
    const int jp  = wrp >> 1;

    u32 aaddr[4], baddr[4];
    {
        const u32 Qb = smem_u32(sQ);
        const u32 Pb = smem_u32(sP);
        // A: row = r0 + (lane&15), k-half = lane>>4
        {
            const u32 row = (u32)(r0 + (lane & 15));
            const u32 hh  = (u32)(lane >> 4);
            const u32 rt  = Qb + row * 128u;
            const u32 x   = row & 7u;
            #pragma unroll
            for (int kc = 0; kc < 4; kc++)
                aaddr[kc] = rt + ((((2u * kc + hh) ^ x)) << 4);
        }
        // B: row = 8*(2jp + (lane>>4)) + (lane&7); k-half = (lane>>3)&1
        {
            const u32 row = 8u * (u32)(2 * jp + (lane >> 4)) + (lane & 7u);
            const u32 hb  = (u32)((lane >> 3) & 1);
            const u32 rt  = Pb + row * 128u;
            const u32 x   = row & 7u;
            #pragma unroll
            for (int kc = 0; kc < 4; kc++)
                baddr[kc] = rt + ((((2u * kc + hb) ^ x)) << 4);
        }
    }

    float acc[2][4];
    #pragma unroll
    for (int j = 0; j < 2; j++)
        #pragma unroll
        for (int r = 0; r < 4; r++) acc[j][r] = 0.0f;

    #pragma unroll
    for (int kc = 0; kc < 4; kc++) {
        u32 ahi[4], alo[4], bh[4], bl[4];
        ldsm4(aaddr[kc],          ahi);
        ldsm4(aaddr[kc] + QPLANE, alo);
        ldsm4(baddr[kc],          bh);
        ldsm4(baddr[kc] + PPLANE, bl);

        #pragma unroll
        for (int jj = 0; jj < 2; jj++) {
            const int o = jj * 2;
            mma_bf16(acc[jj], ahi, bh[o], bh[o + 1]);   // hi*hi
            mma_bf16(acc[jj], ahi, bl[o], bl[o + 1]);   // hi*lo
            mma_bf16(acc[jj], alo, bh[o], bh[o + 1]);   // lo*hi
        }
    }

    // ---- store D fragments: c = r0+gid (+8), m = 8*(2jp+jj) + 2*tig ----
    float* o = out + (size_t)h * 4096;
    #pragma unroll
    for (int jj = 0; jj < 2; jj++) {
        const int m = 8 * (2 * jp + jj) + 2 * tig;
        const int c = r0 + gid;
        *reinterpret_cast<float2*>(o + c * 128 + m) =
            make_float2(acc[jj][0], acc[jj][1]);
        *reinterpret_cast<float2*>(o + (c + 8) * 128 + m) =
            make_float2(acc[jj][2], acc[jj][3]);
    }
}

extern "C" void kernel_launch(void* const* d_in, const int* in_sizes, int n_in,
                              void* d_out, int out_size)
{
    const float* log_dt     = (const float*)d_in[0];
    const float* C          = (const float*)d_in[1];
    const float* log_A_real = (const float*)d_in[2];
    const float* A_imag     = (const float*)d_in[3];
    float*       out        = (float*)d_out;

    const int H = in_sizes[0];   // 1024
    s4d_kernel<<<H, 512>>>(log_dt, C, log_A_real, A_imag, out);
}